// round 3
// baseline (speedup 1.0000x reference)
#include <cuda_runtime.h>
#include <cstdint>
#include <cstddef>

// ---------------------------------------------------------------------------
// GRU-D imputer, fp32, f32x2-packed FMA pipeline, LDS-minimized register tiles.
//   Kernel 1 (recurrent): 128 CTAs x 256 thr, 8 batch rows/CTA, T=1024 steps.
//     Thread tile: 6 outputs x 2 batch rows -> 8 LDS.128 per 24 FFMA2.
//     Stores h[B,T,H] to __device__ scratch.
//   Kernel 2 (heads): 1024 CTAs x 256 thr, 16-row tiles, 6x2 thread tiles;
//     stage-2 mapping transposed (cg = tid&15) for conflict-free LDS.
// ---------------------------------------------------------------------------

namespace {
constexpr int B = 1024, T = 1024, H = 128, C = 6;
constexpr int G3 = 3 * H;        // 384
constexpr int XD = 2 * C + 1;    // 13
constexpr int HP = 140;          // pitch for Ws / hv rows (128 h + 12 gru_in)
constexpr int HOP = 132;         // pitch for h-out staging
constexpr int NB = 8;            // batch rows per CTA (kernel 1)
constexpr int WP2 = 132;         // pitch kernel 2
}

// 512 MB scratch for the h history (module-static; no runtime allocation).
__device__ float g_h[(size_t)B * T * H];

__device__ __forceinline__ void fma2(unsigned long long& d,
                                     unsigned long long a,
                                     unsigned long long b) {
    asm("fma.rn.f32x2 %0, %1, %2, %0;" : "+l"(d) : "l"(a), "l"(b));
}
__device__ __forceinline__ float hsum2(unsigned long long v) {
    float lo, hi;
    asm("mov.b64 {%0, %1}, %2;" : "=f"(lo), "=f"(hi) : "l"(v));
    return lo + hi;
}
__device__ __forceinline__ float sigf(float x) {
    return 1.f / (1.f + __expf(-x));
}

// ---------------------------------------------------------------------------
// Kernel 1: recurrent scan
//   tid = jg*4 + q ; jg in [0,64) output group, q in [0,4) batch pair.
//   Thread owns outputs j = jg + 64*i (i=0..5) for batch rows {2q, 2q+1}:
//     i=0,1 -> r-gate of units {jg, jg+64}; i=2,3 -> z; i=4,5 -> n.
// ---------------------------------------------------------------------------
__global__ void __launch_bounds__(256, 1) grud_recurrent(
    const float* __restrict__ x,
    const float* __restrict__ x_mean,
    const float* __restrict__ dxw_g, const float* __restrict__ dxb_g,
    const float* __restrict__ dhw_g, const float* __restrict__ dhb_g,
    const float* __restrict__ w_ih, const float* __restrict__ w_hh,
    const float* __restrict__ b_ih, const float* __restrict__ b_hh)
{
    extern __shared__ float sm[];
    float* Ws = sm;                    // [384][HP]  combined [w_hh | w_ih]
    float* hv = Ws + G3 * HP;          // [8][HP]    combined [h_dec | x_hat | m]
    float* ho = hv + NB * HP;          // [8][HOP]   h_new staging

    const int tid  = threadIdx.x;
    const int q    = tid & 3;
    const int jg   = tid >> 2;         // 0..63
    const int warp = tid >> 5;
    const int lane = tid & 31;
    const int b0   = blockIdx.x * NB;
    const int r0   = 2 * q, r1 = 2 * q + 1;

    // Fill combined weight tile: cols 0..127 = w_hh, 128..139 = w_ih.
    for (int idx = tid; idx < G3 * H; idx += 256)
        Ws[(idx >> 7) * HP + (idx & 127)] = w_hh[idx];
    for (int idx = tid; idx < G3 * 12; idx += 256)
        Ws[(idx / 12) * HP + H + (idx % 12)] = w_ih[idx];

    // Per-thread constants.
    float bc[4], bhn[2], bin[2];                 // combined r/z biases, n biases
    #pragma unroll
    for (int i = 0; i < 4; i++) {
        int j = jg + 64 * i;
        bc[i] = b_ih[j] + b_hh[j];
    }
    #pragma unroll
    for (int iu = 0; iu < 2; iu++) {
        int j = 256 + jg + 64 * iu;
        bhn[iu] = b_hh[j]; bin[iu] = b_ih[j];
    }
    float dhw[2], dhb[2];
    #pragma unroll
    for (int iu = 0; iu < 2; iu++) { dhw[iu] = dhw_g[jg + 64 * iu]; dhb[iu] = dhb_g[jg + 64 * iu]; }
    float dxw = 0.f, dxb = 0.f, xm = 0.f;
    if (jg < C) { dxw = dxw_g[jg]; dxb = dxb_g[jg]; xm = x_mean[jg]; }

    float hprev[2][2] = {{0.f, 0.f}, {0.f, 0.f}};   // [iu][rr]
    float running[2] = {0.f, 0.f}, xlast[2] = {0.f, 0.f};

    // Prefetch x(t=0).
    const size_t xb0 = ((size_t)(b0 + r0) * T) * XD;
    const size_t xb1 = ((size_t)(b0 + r1) * T) * XD;
    float p_dt[2], p_xv[2] = {0.f, 0.f}, p_mv[2] = {0.f, 0.f};
    p_dt[0] = x[xb0 + 12]; p_dt[1] = x[xb1 + 12];
    if (jg < C) {
        p_xv[0] = x[xb0 + jg];     p_xv[1] = x[xb1 + jg];
        p_mv[0] = x[xb0 + C + jg]; p_mv[1] = x[xb1 + C + jg];
    }

    __syncthreads();

    for (int t = 0; t < T; t++) {
        // Coalesced copy-out of previous step's h (warp w handles batch row w).
        if (t > 0) {
            float4 v = *(const float4*)&ho[warp * HOP + lane * 4];
            *(float4*)&g_h[((size_t)(b0 + warp) * T + (t - 1)) * H + lane * 4] = v;
        }

        const float dtv[2] = {p_dt[0], p_dt[1]};
        const float xvv[2] = {p_xv[0], p_xv[1]};
        const float mvv[2] = {p_mv[0], p_mv[1]};

        // Prefetch x(t+1) — consumed next iteration; hides LDG latency behind GEMM.
        if (t + 1 < T) {
            size_t o0 = xb0 + (size_t)(t + 1) * XD, o1 = xb1 + (size_t)(t + 1) * XD;
            p_dt[0] = x[o0 + 12]; p_dt[1] = x[o1 + 12];
            if (jg < C) {
                p_xv[0] = x[o0 + jg];     p_xv[1] = x[o1 + jg];
                p_mv[0] = x[o0 + C + jg]; p_mv[1] = x[o1 + C + jg];
            }
        }

        // h_dec = gamma_h * h_prev (4 states in registers).
        float hd[2][2];
        #pragma unroll
        for (int rr = 0; rr < 2; rr++) {
            int row = r0 + rr;
            #pragma unroll
            for (int iu = 0; iu < 2; iu++) {
                float g = __expf(-fmaxf(fmaf(dtv[rr], dhw[iu], dhb[iu]), 0.f));
                float v = g * hprev[iu][rr];
                hd[iu][rr] = v;
                hv[row * HP + jg + 64 * iu] = v;
            }
        }
        // Input scans + x_hat (threads jg<6 own feature c=jg of rows r0,r1).
        if (jg < C) {
            #pragma unroll
            for (int rr = 0; rr < 2; rr++) {
                int row = r0 + rr;
                float xv = xvv[rr], m = mvv[rr];
                bool obs = (m > 0.5f);
                running[rr] = obs ? 0.f : (running[rr] + dtv[rr]);
                float gx = __expf(-fmaxf(fmaf(running[rr], dxw, dxb), 0.f));
                xlast[rr] = obs ? xv : xlast[rr];
                float xh = m * xv + (1.f - m) * (gx * xlast[rr] + (1.f - gx) * xm);
                hv[row * HP + H + jg]     = xh;   // gru_in[0:6]  = x_hat
                hv[row * HP + H + C + jg] = m;    // gru_in[6:12] = m
            }
        }
        __syncthreads();

        // GEMM: 6 outputs x 2 rows per thread; K=140 in 16B chunks.
        // acch[i] (i<4): full r/z sums (gh+gi). acch[4..5]: gh_n only.
        // acci[iu]: gi_n (kb 32..34) — n = tanh(gi_n + r*gh_n).
        unsigned long long acch[6][2], acci[2][2];
        #pragma unroll
        for (int i = 0; i < 6; i++) { acch[i][0] = 0ull; acch[i][1] = 0ull; }
        acci[0][0] = acci[0][1] = acci[1][0] = acci[1][1] = 0ull;

        const float* h0 = &hv[r0 * HP];
        const float* h1 = &hv[r1 * HP];
        const float* wb = &Ws[jg * HP];
        #pragma unroll
        for (int kb = 0; kb < 32; kb++) {
            ulonglong2 hp0 = *(const ulonglong2*)&h0[4 * kb];
            ulonglong2 hp1 = *(const ulonglong2*)&h1[4 * kb];
            #pragma unroll
            for (int i = 0; i < 6; i++) {
                ulonglong2 wp = *(const ulonglong2*)&wb[i * 64 * HP + 4 * kb];
                fma2(acch[i][0], hp0.x, wp.x); fma2(acch[i][0], hp0.y, wp.y);
                fma2(acch[i][1], hp1.x, wp.x); fma2(acch[i][1], hp1.y, wp.y);
            }
        }
        #pragma unroll
        for (int kb = 32; kb < 35; kb++) {
            ulonglong2 hp0 = *(const ulonglong2*)&h0[4 * kb];
            ulonglong2 hp1 = *(const ulonglong2*)&h1[4 * kb];
            #pragma unroll
            for (int i = 0; i < 4; i++) {           // r,z: fold gi into acch
                ulonglong2 wp = *(const ulonglong2*)&wb[i * 64 * HP + 4 * kb];
                fma2(acch[i][0], hp0.x, wp.x); fma2(acch[i][0], hp0.y, wp.y);
                fma2(acch[i][1], hp1.x, wp.x); fma2(acch[i][1], hp1.y, wp.y);
            }
            #pragma unroll
            for (int iu = 0; iu < 2; iu++) {        // n: gi kept separate
                ulonglong2 wp = *(const ulonglong2*)&wb[(4 + iu) * 64 * HP + 4 * kb];
                fma2(acci[iu][0], hp0.x, wp.x); fma2(acci[iu][0], hp0.y, wp.y);
                fma2(acci[iu][1], hp1.x, wp.x); fma2(acci[iu][1], hp1.y, wp.y);
            }
        }

        // Gates + state update, fully in registers.
        #pragma unroll
        for (int rr = 0; rr < 2; rr++) {
            int row = r0 + rr;
            #pragma unroll
            for (int iu = 0; iu < 2; iu++) {
                float r   = sigf(hsum2(acch[iu][rr])     + bc[iu]);
                float z   = sigf(hsum2(acch[2 + iu][rr]) + bc[2 + iu]);
                float ghn = hsum2(acch[4 + iu][rr]) + bhn[iu];
                float gin = hsum2(acci[iu][rr])     + bin[iu];
                float n   = tanhf(fmaf(r, ghn, gin));
                float hn  = fmaf(z, hd[iu][rr] - n, n);   // (1-z)*n + z*h_dec
                hprev[iu][rr] = hn;
                ho[row * HOP + jg + 64 * iu] = hn;
            }
        }
        __syncthreads();
    }
    // Final copy-out for t = T-1.
    {
        float4 v = *(const float4*)&ho[warp * HOP + lane * 4];
        *(float4*)&g_h[((size_t)(b0 + warp) * T + (T - 1)) * H + lane * 4] = v;
    }
}

// ---------------------------------------------------------------------------
// Kernel 2: output heads over 1M rows; 16-row tiles, 6x2 thread tiles.
//   Stage 1: tid = jg*8 + rp ; jg in [0,32), rp in [0,8). Rows {rp, rp+8}.
//     Outputs j = jg + 32*i: i<4 -> w1 rows (H=128); i=4,5 -> wu1 rows (64).
//   Stage 2: cg = tid&15 (channel), rr2 = tid>>4 (row) — conflict-free
//     16-way-broadcast row reads, coalesced channel-contiguous stores.
// ---------------------------------------------------------------------------
__global__ void __launch_bounds__(256, 1) grud_heads(
    const float* __restrict__ w1,  const float* __restrict__ b1,
    const float* __restrict__ w2,  const float* __restrict__ b2,
    const float* __restrict__ wu1, const float* __restrict__ bu1,
    const float* __restrict__ wu2, const float* __restrict__ bu2,
    float* __restrict__ out_pred, float* __restrict__ out_unc)
{
    extern __shared__ float sm[];
    float* w1s  = sm;                     // [128][WP2]
    float* wu1s = w1s  + H * WP2;         // [64][WP2]
    float* w2s  = wu1s + 64 * WP2;        // [6][WP2]
    float* wu2s = w2s  + C * WP2;         // [6][68]
    float* b1s  = wu2s + C * 68;          // [128]
    float* bu1s = b1s  + H;               // [64]
    float* hts  = bu1s + 64;              // [16][WP2]
    float* o1s  = hts  + 16 * WP2;        // [16][WP2]
    float* u1s  = o1s  + 16 * WP2;        // [16][68]

    const int tid = threadIdx.x;
    const int rp  = tid & 7;
    const int jg  = tid >> 3;             // 0..31
    const int cg  = tid & 15;             // stage-2 channel group
    const int rr2 = tid >> 4;             // stage-2 row 0..15

    for (int idx = tid; idx < H * H;  idx += 256) w1s [(idx >> 7) * WP2 + (idx & 127)] = w1[idx];
    for (int idx = tid; idx < 64 * H; idx += 256) wu1s[(idx >> 7) * WP2 + (idx & 127)] = wu1[idx];
    for (int idx = tid; idx < C * H;  idx += 256) w2s [(idx >> 7) * WP2 + (idx & 127)] = w2[idx];
    for (int idx = tid; idx < C * 64; idx += 256) wu2s[(idx >> 6) * 68  + (idx & 63)]  = wu2[idx];
    if (tid < H) b1s[tid] = b1[tid];
    if (tid >= 128 && tid < 192) bu1s[tid - 128] = bu1[tid - 128];

    float bias1[6];
    #pragma unroll
    for (int i = 0; i < 4; i++) bias1[i] = b1[jg + 32 * i];
    bias1[4] = bu1[jg]; bias1[5] = bu1[jg + 32];
    float bias2 = 0.f;
    if (cg < C) bias2 = b2[cg];
    else if (cg >= 8 && cg < 8 + C) bias2 = bu2[cg - 8];
    __syncthreads();

    const int tiles_per_cta = (B * T / 16) / gridDim.x;
    const int tbase = blockIdx.x * tiles_per_cta;

    for (int g = 0; g < tiles_per_cta; g++) {
        const size_t row0 = (size_t)(tbase + g) * 16;
        // Coalesced h tile load: 512 float4 across 256 threads.
        #pragma unroll
        for (int j = 0; j < 2; j++) {
            int v = tid * 2 + j;
            int rw = v >> 5, k4 = v & 31;
            float4 hval = *(const float4*)&g_h[(row0 + rw) * H + 4 * k4];
            *(float4*)&hts[rw * WP2 + 4 * k4] = hval;
        }
        __syncthreads();

        unsigned long long a[6][2];
        #pragma unroll
        for (int i = 0; i < 6; i++) { a[i][0] = 0ull; a[i][1] = 0ull; }
        const float* h0 = &hts[rp * WP2];
        const float* h1 = &hts[(rp + 8) * WP2];
        #pragma unroll
        for (int kb = 0; kb < 32; kb++) {
            ulonglong2 hp0 = *(const ulonglong2*)&h0[4 * kb];
            ulonglong2 hp1 = *(const ulonglong2*)&h1[4 * kb];
            #pragma unroll
            for (int i = 0; i < 4; i++) {
                ulonglong2 wp = *(const ulonglong2*)&w1s[(jg + 32 * i) * WP2 + 4 * kb];
                fma2(a[i][0], hp0.x, wp.x); fma2(a[i][0], hp0.y, wp.y);
                fma2(a[i][1], hp1.x, wp.x); fma2(a[i][1], hp1.y, wp.y);
            }
            #pragma unroll
            for (int i = 4; i < 6; i++) {
                ulonglong2 wp = *(const ulonglong2*)&wu1s[(jg + 32 * (i - 4)) * WP2 + 4 * kb];
                fma2(a[i][0], hp0.x, wp.x); fma2(a[i][0], hp0.y, wp.y);
                fma2(a[i][1], hp1.x, wp.x); fma2(a[i][1], hp1.y, wp.y);
            }
        }
        #pragma unroll
        for (int rr = 0; rr < 2; rr++) {
            int row = rp + 8 * rr;
            #pragma unroll
            for (int i = 0; i < 4; i++)
                o1s[row * WP2 + jg + 32 * i] = fmaxf(hsum2(a[i][rr]) + bias1[i], 0.f);
            u1s[row * 68 + jg]      = fmaxf(hsum2(a[4][rr]) + bias1[4], 0.f);
            u1s[row * 68 + jg + 32] = fmaxf(hsum2(a[5][rr]) + bias1[5], 0.f);
        }
        __syncthreads();

        // Stage 2: project to C=6 pred / unc channels.
        // cg<6: pred; cg in [8,14): unc. Row reads are 16-way broadcast
        // (2 distinct rr2 per warp) -> conflict-free.
        if (cg < C) {
            unsigned long long acc = 0ull;
            const float* o = &o1s[rr2 * WP2];
            const float* w = &w2s[cg * WP2];
            #pragma unroll
            for (int kb = 0; kb < 32; kb++) {
                ulonglong2 op = *(const ulonglong2*)&o[4 * kb];
                ulonglong2 wp = *(const ulonglong2*)&w[4 * kb];
                fma2(acc, op.x, wp.x); fma2(acc, op.y, wp.y);
            }
            out_pred[(row0 + rr2) * C + cg] = hsum2(acc) + bias2;
        } else if (cg >= 8 && cg < 8 + C) {
            unsigned long long acc = 0ull;
            const float* u = &u1s[rr2 * 68];
            const float* w = &wu2s[(cg - 8) * 68];
            #pragma unroll
            for (int kb = 0; kb < 16; kb++) {
                ulonglong2 up = *(const ulonglong2*)&u[4 * kb];
                ulonglong2 wp = *(const ulonglong2*)&w[4 * kb];
                fma2(acc, up.x, wp.x); fma2(acc, up.y, wp.y);
            }
            float s = hsum2(acc) + bias2;
            out_unc[(row0 + rr2) * C + (cg - 8)] = (s > 20.f) ? s : log1pf(__expf(s));
        }
        __syncthreads();
    }
}

// ---------------------------------------------------------------------------
// Launch
// ---------------------------------------------------------------------------
extern "C" void kernel_launch(void* const* d_in, const int* in_sizes, int n_in,
                              void* d_out, int out_size) {
    const float* x      = (const float*)d_in[0];
    const float* x_mean = (const float*)d_in[1];
    const float* dxw    = (const float*)d_in[2];
    const float* dxb    = (const float*)d_in[3];
    const float* dhw    = (const float*)d_in[4];
    const float* dhb    = (const float*)d_in[5];
    const float* w_ih   = (const float*)d_in[6];
    const float* w_hh   = (const float*)d_in[7];
    const float* b_ih   = (const float*)d_in[8];
    const float* b_hh   = (const float*)d_in[9];
    const float* w1     = (const float*)d_in[10];
    const float* b1     = (const float*)d_in[11];
    const float* w2     = (const float*)d_in[12];
    const float* b2     = (const float*)d_in[13];
    const float* wu1    = (const float*)d_in[14];
    const float* bu1    = (const float*)d_in[15];
    const float* wu2    = (const float*)d_in[16];
    const float* bu2    = (const float*)d_in[17];

    float* pred = (float*)d_out;
    float* unc  = pred + (size_t)B * T * C;

    const int sm1 = (G3 * HP + NB * HP + NB * HOP) * 4;                      // 223,744 B
    const int sm2 = (H * WP2 + 64 * WP2 + C * WP2 + C * 68 + H + 64 +
                     16 * WP2 + 16 * WP2 + 16 * 68) * 4;                     // 128,192 B

    cudaFuncSetAttribute(grud_recurrent, cudaFuncAttributeMaxDynamicSharedMemorySize, sm1);
    cudaFuncSetAttribute(grud_heads,     cudaFuncAttributeMaxDynamicSharedMemorySize, sm2);

    grud_recurrent<<<B / NB, 256, sm1>>>(x, x_mean, dxw, dxb, dhw, dhb,
                                         w_ih, w_hh, b_ih, b_hh);
    grud_heads<<<1024, 256, sm2>>>(w1, b1, w2, b2, wu1, bu1, wu2, bu2, pred, unc);
}